// round 3
// baseline (speedup 1.0000x reference)
#include <cuda_runtime.h>
#include <cuda_fp16.h>
#include <cstdint>
#include <cstddef>

#define NE 16
#define HD 2048
#define ID 1536
#define TT 32768

// ---------------- device scratch (allocation-free rule) -------------------------
__device__ __half g_xh[(size_t)TT * HD];     // x in fp16                (128MB)
__device__ __half g_gate[(size_t)TT * ID];   // raw gate projection      ( 96MB)
__device__ __half g_hid[(size_t)TT * ID];    // silu(gate)*up            ( 96MB)

// ---------------- helpers -------------------------------------------------------
__device__ __forceinline__ uint32_t smem_u32(const void* p) {
    uint32_t a;
    asm("{ .reg .u64 t; cvta.to.shared.u64 t, %1; cvt.u32.u64 %0, t; }" : "=r"(a) : "l"(p));
    return a;
}
__device__ __forceinline__ void cp16(uint32_t dst, const void* src) {
    asm volatile("cp.async.cg.shared.global [%0], [%1], 16;" :: "r"(dst), "l"(src));
}
__device__ __forceinline__ void ldsm4(uint32_t& r0, uint32_t& r1, uint32_t& r2,
                                      uint32_t& r3, uint32_t a) {
    asm volatile("ldmatrix.sync.aligned.m8n8.x4.shared.b16 {%0,%1,%2,%3}, [%4];"
                 : "=r"(r0), "=r"(r1), "=r"(r2), "=r"(r3) : "r"(a));
}
__device__ __forceinline__ void ldsm4t(uint32_t& r0, uint32_t& r1, uint32_t& r2,
                                       uint32_t& r3, uint32_t a) {
    asm volatile("ldmatrix.sync.aligned.m8n8.x4.trans.shared.b16 {%0,%1,%2,%3}, [%4];"
                 : "=r"(r0), "=r"(r1), "=r"(r2), "=r"(r3) : "r"(a));
}
__device__ __forceinline__ void mma16816(float* c, uint32_t a0, uint32_t a1, uint32_t a2,
                                         uint32_t a3, uint32_t b0, uint32_t b1) {
    asm volatile(
        "mma.sync.aligned.m16n8k16.row.col.f32.f16.f16.f32 "
        "{%0,%1,%2,%3}, {%4,%5,%6,%7}, {%8,%9}, {%0,%1,%2,%3};"
        : "+f"(c[0]), "+f"(c[1]), "+f"(c[2]), "+f"(c[3])
        : "r"(a0), "r"(a1), "r"(a2), "r"(a3), "r"(b0), "r"(b1));
}
__device__ __forceinline__ uint32_t pk(float a, float b) {
    __half2 h = __floats2half2_rn(a, b);
    return *reinterpret_cast<uint32_t*>(&h);
}
__device__ __forceinline__ float silu_f(float x) { return x / (1.0f + __expf(-x)); }

// ---------------- x fp32 -> fp16 ------------------------------------------------
__global__ void cvt_x(const float4* __restrict__ x, int n4) {
    int i = blockIdx.x * blockDim.x + threadIdx.x;
    if (i < n4) {
        float4 v = x[i];
        uint2 o;
        o.x = pk(v.x, v.y);
        o.y = pk(v.z, v.w);
        *reinterpret_cast<uint2*>(g_xh + (size_t)i * 4) = o;
    }
}

// ---------------- grouped GEMM (mma.sync fp16, fp32 accum) ----------------------
// CTA tile 128x128, K-chunk 64, 8 warps (warp tile 64x32), 2-stage pipeline.
// A: fp16 K-major, cp.async.  B: fp32 [K,N] N-contiguous, LDG->cvt->STS.
// MODE 0: write fp16 raw   (gate)
// MODE 1: write fp16 silu(G)*acc, reading fp16 G at same coords  (up, fused SiLU)
// MODE 2: write fp32       (down)
static constexpr int SMEM_DYN = 4 * 16384 + 128;

template <int KDIM, int NDIM, int MODE>
__global__ void __launch_bounds__(256, 1)
gemm_moe(const __half* __restrict__ Ag, const float* __restrict__ Ball,
         void* __restrict__ Cv, const __half* __restrict__ Gv,
         const int* __restrict__ gs) {
    extern __shared__ char dsm[];
    __shared__ int s_cum[NE];

    const int tid = threadIdx.x;
    if (tid == 0) {
        int c = 0;
#pragma unroll
        for (int k = 0; k < NE; ++k) { s_cum[k] = c; c += gs[k]; }
    }
    __syncthreads();

    const int m0 = blockIdx.y * 128;
    const int n0 = blockIdx.x * 128;
    int e = 0;
#pragma unroll
    for (int k = 1; k < NE; ++k) e += (s_cum[k] <= m0) ? 1 : 0;

    const float* Bg = Ball + (size_t)e * KDIM * NDIM + n0;
    const __half* Ap = Ag + (size_t)m0 * KDIM;

    const uint32_t base = (smem_u32(dsm) + 127u) & ~127u;
    const uint32_t sA[2] = {base, base + 16384};
    const uint32_t sB[2] = {base + 32768, base + 49152};

    const int lane = tid & 31, wid = tid >> 5;
    const int wm = wid >> 2, wn = wid & 3;

    // ---- B staging: fp32 LDG -> fp16 regs ----
    uint4 brh[2][4];
    auto ldgB = [&](int set, int ch) {
        const float* p = Bg + (size_t)ch * 64 * NDIM;
#pragma unroll
        for (int it = 0; it < 4; ++it) {
            int t4 = tid + it * 256;
            int k = t4 >> 4, ng = t4 & 15;
            const float* q = p + (size_t)k * NDIM + ng * 8;
            float4 x0 = *(const float4*)q;
            float4 x1 = *(const float4*)(q + 4);
            brh[set][it].x = pk(x0.x, x0.y);
            brh[set][it].y = pk(x0.z, x0.w);
            brh[set][it].z = pk(x1.x, x1.y);
            brh[set][it].w = pk(x1.z, x1.w);
        }
    };
    auto stsB = [&](int set, int stg) {
#pragma unroll
        for (int it = 0; it < 4; ++it) {
            int t4 = tid + it * 256;
            int k = t4 >> 4, ng = t4 & 15;
            uint32_t addr = sB[stg] + k * 256 + ((ng ^ (k & 7)) << 4);
            asm volatile("st.shared.v4.b32 [%0], {%1,%2,%3,%4};"
                         :: "r"(addr), "r"(brh[set][it].x), "r"(brh[set][it].y),
                            "r"(brh[set][it].z), "r"(brh[set][it].w));
        }
    };
    auto cpA = [&](int stg, int ch) {
        const __half* p = Ap + ch * 64;
#pragma unroll
        for (int it = 0; it < 4; ++it) {
            int g = tid + it * 256;
            int r = g >> 3, q = g & 7;
            uint32_t dst = sA[stg] + r * 128 + ((q ^ (r & 7)) << 4);
            cp16(dst, p + (size_t)r * KDIM + q * 8);
        }
        asm volatile("cp.async.commit_group;" ::: "memory");
    };

    float acc[4][4][4];
#pragma unroll
    for (int a = 0; a < 4; ++a)
#pragma unroll
        for (int b = 0; b < 4; ++b)
#pragma unroll
            for (int c = 0; c < 4; ++c) acc[a][b][c] = 0.f;

    auto compute = [&](int stg) {
        const uint32_t Ab = sA[stg], Bb = sB[stg];
        const int sub = lane >> 3, lr = lane & 7;
#pragma unroll
        for (int ks = 0; ks < 4; ++ks) {
            uint32_t bfr[8];
#pragma unroll
            for (int np = 0; np < 2; ++np) {
                int krow = ks * 16 + (sub & 1) * 8 + lr;
                int ng = wn * 4 + np * 2 + (sub >> 1);
                uint32_t addr = Bb + krow * 256 + ((ng ^ (krow & 7)) << 4);
                ldsm4t(bfr[np * 4 + 0], bfr[np * 4 + 1], bfr[np * 4 + 2],
                       bfr[np * 4 + 3], addr);
            }
#pragma unroll
            for (int mb = 0; mb < 4; ++mb) {
                int row = wm * 64 + mb * 16 + (sub & 1) * 8 + lr;
                int q = ks * 2 + (sub >> 1);
                uint32_t addr = Ab + row * 128 + ((q ^ (row & 7)) << 4);
                uint32_t a0, a1, a2, a3;
                ldsm4(a0, a1, a2, a3, addr);
#pragma unroll
                for (int np = 0; np < 2; ++np) {
                    mma16816(acc[mb][np * 2 + 0], a0, a1, a2, a3,
                             bfr[np * 4 + 0], bfr[np * 4 + 1]);
                    mma16816(acc[mb][np * 2 + 1], a0, a1, a2, a3,
                             bfr[np * 4 + 2], bfr[np * 4 + 3]);
                }
            }
        }
    };

    const int nch = KDIM / 64;

    // ---- prologue ----
    ldgB(0, 0);
    ldgB(1, 1);
    stsB(0, 0);
    cpA(0, 0);
    asm volatile("cp.async.wait_group 0;" ::: "memory");
    __syncthreads();

    // ---- mainloop ----
#pragma unroll 1
    for (int i = 0; i < nch; ++i) {
        const int stg = i & 1;
        if (i + 1 < nch) { stsB((i + 1) & 1, (i + 1) & 1); cpA((i + 1) & 1, i + 1); }
        if (i + 2 < nch) { ldgB(i & 1, i + 2); }
        compute(stg);
        if (i + 1 < nch) {
            asm volatile("cp.async.wait_group 0;" ::: "memory");
            __syncthreads();
        }
    }

    // ---- epilogue ----
    const int r0 = m0 + wm * 64 + (lane >> 2);
    const int c0 = n0 + wn * 32 + (lane & 3) * 2;

#pragma unroll
    for (int mb = 0; mb < 4; ++mb) {
#pragma unroll
        for (int nb = 0; nb < 4; ++nb) {
            const int rr = r0 + mb * 16;
            const int cc = c0 + nb * 8;
            const size_t o0 = (size_t)rr * NDIM + cc;
            const size_t o1 = (size_t)(rr + 8) * NDIM + cc;
            float* a = acc[mb][nb];
            if (MODE == 0) {
                __half* C = (__half*)Cv;
                *(uint32_t*)(C + o0) = pk(a[0], a[1]);
                *(uint32_t*)(C + o1) = pk(a[2], a[3]);
            } else if (MODE == 1) {
                __half* C = (__half*)Cv;
                __half2 g0 = *(const __half2*)(Gv + o0);
                __half2 g1 = *(const __half2*)(Gv + o1);
                float2 f0 = __half22float2(g0);
                float2 f1 = __half22float2(g1);
                *(uint32_t*)(C + o0) = pk(silu_f(f0.x) * a[0], silu_f(f0.y) * a[1]);
                *(uint32_t*)(C + o1) = pk(silu_f(f1.x) * a[2], silu_f(f1.y) * a[3]);
            } else {
                float* C = (float*)Cv;
                *(float2*)(C + o0) = make_float2(a[0], a[1]);
                *(float2*)(C + o1) = make_float2(a[2], a[3]);
            }
        }
    }
}

// ---------------- host launcher -------------------------------------------------
extern "C" void kernel_launch(void* const* d_in, const int* in_sizes, int n_in,
                              void* d_out, int out_size) {
    const float* x  = (const float*)d_in[0];
    const float* gw = (const float*)d_in[1];
    const float* uw = (const float*)d_in[2];
    const float* dw = (const float*)d_in[3];
    const int*   gs = (const int*)d_in[4];
    float* out = (float*)d_out;

    // Resolve REAL device addresses of the __device__ scratch globals.
    // (Passing the symbol directly from host code passes the host shadow; on
    // GB300 with ATS that silently reads zero-filled host memory.)
    void *p_xh = nullptr, *p_gate = nullptr, *p_hid = nullptr;
    cudaGetSymbolAddress(&p_xh, g_xh);
    cudaGetSymbolAddress(&p_gate, g_gate);
    cudaGetSymbolAddress(&p_hid, g_hid);
    __half* xh   = (__half*)p_xh;
    __half* gate = (__half*)p_gate;
    __half* hid  = (__half*)p_hid;

    cudaFuncSetAttribute(gemm_moe<HD, ID, 0>,
                         cudaFuncAttributeMaxDynamicSharedMemorySize, SMEM_DYN);
    cudaFuncSetAttribute(gemm_moe<HD, ID, 1>,
                         cudaFuncAttributeMaxDynamicSharedMemorySize, SMEM_DYN);
    cudaFuncSetAttribute(gemm_moe<ID, HD, 2>,
                         cudaFuncAttributeMaxDynamicSharedMemorySize, SMEM_DYN);

    const int n4 = (TT * HD) / 4;
    cvt_x<<<(n4 + 255) / 256, 256>>>((const float4*)x, n4);

    // gate = x @ gate_w            -> g_gate (fp16)
    gemm_moe<HD, ID, 0><<<dim3(ID / 128, TT / 128), 256, SMEM_DYN>>>(
        xh, gw, gate, nullptr, gs);
    // hid = silu(gate) * (x @ up_w) -> g_hid (fp16, fused epilogue)
    gemm_moe<HD, ID, 1><<<dim3(ID / 128, TT / 128), 256, SMEM_DYN>>>(
        xh, uw, hid, gate, gs);
    // out = hid @ down_w           -> out (fp32)
    gemm_moe<ID, HD, 2><<<dim3(HD / 128, TT / 128), 256, SMEM_DYN>>>(
        hid, dw, out, nullptr, gs);
}

// round 4
// speedup vs baseline: 2.2922x; 2.2922x over previous
#include <cuda_runtime.h>
#include <cuda_fp16.h>
#include <cstdint>
#include <cstddef>

#define NE 16
#define HD 2048
#define ID 1536
#define TT 32768

// ---------------- device scratch (allocation-free rule) -------------------------
__device__ __half g_xh[(size_t)TT * HD];                  // x fp16          (128MB)
__device__ __half g_gate[(size_t)TT * ID];                // gate proj fp16  ( 96MB)
__device__ __half g_hid[(size_t)TT * ID];                 // silu(g)*up fp16 ( 96MB)
__device__ __half g_wh[(size_t)NE * 3 * HD * ID];         // fp16 weights    (302MB)

// ---------------- helpers -------------------------------------------------------
__device__ __forceinline__ uint32_t smem_u32(const void* p) {
    uint32_t a;
    asm("{ .reg .u64 t; cvta.to.shared.u64 t, %1; cvt.u32.u64 %0, t; }" : "=r"(a) : "l"(p));
    return a;
}
__device__ __forceinline__ void cp16(uint32_t dst, const void* src) {
    asm volatile("cp.async.cg.shared.global [%0], [%1], 16;" :: "r"(dst), "l"(src));
}
__device__ __forceinline__ void ldsm4(uint32_t& r0, uint32_t& r1, uint32_t& r2,
                                      uint32_t& r3, uint32_t a) {
    asm volatile("ldmatrix.sync.aligned.m8n8.x4.shared.b16 {%0,%1,%2,%3}, [%4];"
                 : "=r"(r0), "=r"(r1), "=r"(r2), "=r"(r3) : "r"(a));
}
__device__ __forceinline__ void ldsm4t(uint32_t& r0, uint32_t& r1, uint32_t& r2,
                                       uint32_t& r3, uint32_t a) {
    asm volatile("ldmatrix.sync.aligned.m8n8.x4.trans.shared.b16 {%0,%1,%2,%3}, [%4];"
                 : "=r"(r0), "=r"(r1), "=r"(r2), "=r"(r3) : "r"(a));
}
__device__ __forceinline__ void mma16816(float* c, uint32_t a0, uint32_t a1, uint32_t a2,
                                         uint32_t a3, uint32_t b0, uint32_t b1) {
    asm volatile(
        "mma.sync.aligned.m16n8k16.row.col.f32.f16.f16.f32 "
        "{%0,%1,%2,%3}, {%4,%5,%6,%7}, {%8,%9}, {%0,%1,%2,%3};"
        : "+f"(c[0]), "+f"(c[1]), "+f"(c[2]), "+f"(c[3])
        : "r"(a0), "r"(a1), "r"(a2), "r"(a3), "r"(b0), "r"(b1));
}
__device__ __forceinline__ uint32_t pk(float a, float b) {
    __half2 h = __floats2half2_rn(a, b);
    return *reinterpret_cast<uint32_t*>(&h);
}
__device__ __forceinline__ float silu_f(float x) { return x / (1.0f + __expf(-x)); }

// ---------------- fp32 -> fp16 converters ---------------------------------------
__global__ void cvt_f2h(const float4* __restrict__ src, __half* __restrict__ dst,
                        int n4) {
    int i = blockIdx.x * blockDim.x + threadIdx.x;
    if (i < n4) {
        float4 v = src[i];
        uint2 o;
        o.x = pk(v.x, v.y);
        o.y = pk(v.z, v.w);
        *reinterpret_cast<uint2*>(dst + (size_t)i * 4) = o;
    }
}

// ---------------- grouped GEMM (mma.sync fp16, fp32 accum) ----------------------
// CTA tile 128x128, K-chunk 64, 8 warps (warp tile 64x32), 3-stage cp.async
// pipeline, 2 CTAs/SM.  A fp16 K-major, B fp16 [K,N] N-contiguous.
// MODE 0: write fp16 raw (gate)
// MODE 1: write fp16 silu(G)*acc reading G           (up, fused SiLU)
// MODE 2: write fp32                                 (down)
static constexpr int STG_A = 16384;            // 128 x 64 fp16
static constexpr int STG_B = 32768 - 16384;    // 64 x 128 fp16 (16KB)
static constexpr int STG = STG_A + STG_B;      // 32KB
static constexpr int SMEM_DYN = 3 * STG + 128;

template <int KDIM, int NDIM, int MODE>
__global__ void __launch_bounds__(256, 2)
gemm_moe(const __half* __restrict__ Ag, const __half* __restrict__ Ball,
         void* __restrict__ Cv, const __half* __restrict__ Gv,
         const int* __restrict__ gs) {
    extern __shared__ char dsm[];
    __shared__ int s_cum[NE];

    const int tid = threadIdx.x;
    if (tid == 0) {
        int c = 0;
#pragma unroll
        for (int k = 0; k < NE; ++k) { s_cum[k] = c; c += gs[k]; }
    }
    __syncthreads();

    const int m0 = blockIdx.y * 128;
    const int n0 = blockIdx.x * 128;
    int e = 0;
#pragma unroll
    for (int k = 1; k < NE; ++k) e += (s_cum[k] <= m0) ? 1 : 0;

    const __half* Bg = Ball + (size_t)e * KDIM * NDIM + n0;
    const __half* Ap = Ag + (size_t)m0 * KDIM;

    const uint32_t base = (smem_u32(dsm) + 127u) & ~127u;

    const int lane = tid & 31, wid = tid >> 5;
    const int wm = wid >> 2, wn = wid & 3;

    // ---- stage loaders (all cp.async) ----
    auto load_stage = [&](int slot, int ch) {
        const uint32_t sA = base + slot * STG;
        const uint32_t sB = sA + STG_A;
        const __half* ap = Ap + ch * 64;
#pragma unroll
        for (int it = 0; it < 4; ++it) {
            int g = tid + it * 256;
            int r = g >> 3, q = g & 7;                       // 128 rows x 8 chunks
            cp16(sA + r * 128 + ((q ^ (r & 7)) << 4),
                 ap + (size_t)r * KDIM + q * 8);
        }
        const __half* bp = Bg + (size_t)(ch * 64) * NDIM;
#pragma unroll
        for (int it = 0; it < 4; ++it) {
            int g = tid + it * 256;
            int r = g >> 4, c = g & 15;                      // 64 rows x 16 chunks
            cp16(sB + r * 256 + ((c ^ (r & 7)) << 4),
                 bp + (size_t)r * NDIM + c * 8);
        }
        asm volatile("cp.async.commit_group;" ::: "memory");
    };

    float acc[4][4][4];
#pragma unroll
    for (int a = 0; a < 4; ++a)
#pragma unroll
        for (int b = 0; b < 4; ++b)
#pragma unroll
            for (int c = 0; c < 4; ++c) acc[a][b][c] = 0.f;

    auto compute = [&](int slot) {
        const uint32_t Ab = base + slot * STG;
        const uint32_t Bb = Ab + STG_A;
        const int sub = lane >> 3, lr = lane & 7;
#pragma unroll
        for (int ks = 0; ks < 4; ++ks) {
            uint32_t bfr[8];
#pragma unroll
            for (int np = 0; np < 2; ++np) {
                int krow = ks * 16 + (sub & 1) * 8 + lr;
                int ng = wn * 4 + np * 2 + (sub >> 1);
                uint32_t addr = Bb + krow * 256 + ((ng ^ (krow & 7)) << 4);
                ldsm4t(bfr[np * 4 + 0], bfr[np * 4 + 1], bfr[np * 4 + 2],
                       bfr[np * 4 + 3], addr);
            }
#pragma unroll
            for (int mb = 0; mb < 4; ++mb) {
                int row = wm * 64 + mb * 16 + (sub & 1) * 8 + lr;
                int q = ks * 2 + (sub >> 1);
                uint32_t addr = Ab + row * 128 + ((q ^ (row & 7)) << 4);
                uint32_t a0, a1, a2, a3;
                ldsm4(a0, a1, a2, a3, addr);
#pragma unroll
                for (int np = 0; np < 2; ++np) {
                    mma16816(acc[mb][np * 2 + 0], a0, a1, a2, a3,
                             bfr[np * 4 + 0], bfr[np * 4 + 1]);
                    mma16816(acc[mb][np * 2 + 1], a0, a1, a2, a3,
                             bfr[np * 4 + 2], bfr[np * 4 + 3]);
                }
            }
        }
    };

    const int nch = KDIM / 64;

    // ---- prologue: stages 0,1 in flight ----
    load_stage(0, 0);
    load_stage(1, 1);

    // ---- mainloop: 3-slot rotation, one load overlapped with compute ----
#pragma unroll 1
    for (int i = 0; i < nch; ++i) {
        if (i + 1 < nch) asm volatile("cp.async.wait_group 1;" ::: "memory");
        else             asm volatile("cp.async.wait_group 0;" ::: "memory");
        __syncthreads();
        if (i + 2 < nch) load_stage((i + 2) % 3, i + 2);
        compute(i % 3);
    }

    // ---- epilogue ----
    const int r0 = m0 + wm * 64 + (lane >> 2);
    const int c0 = n0 + wn * 32 + (lane & 3) * 2;

#pragma unroll
    for (int mb = 0; mb < 4; ++mb) {
#pragma unroll
        for (int nb = 0; nb < 4; ++nb) {
            const int rr = r0 + mb * 16;
            const int cc = c0 + nb * 8;
            const size_t o0 = (size_t)rr * NDIM + cc;
            const size_t o1 = (size_t)(rr + 8) * NDIM + cc;
            float* a = acc[mb][nb];
            if (MODE == 0) {
                __half* C = (__half*)Cv;
                *(uint32_t*)(C + o0) = pk(a[0], a[1]);
                *(uint32_t*)(C + o1) = pk(a[2], a[3]);
            } else if (MODE == 1) {
                __half* C = (__half*)Cv;
                __half2 g0 = *(const __half2*)(Gv + o0);
                __half2 g1 = *(const __half2*)(Gv + o1);
                float2 f0 = __half22float2(g0);
                float2 f1 = __half22float2(g1);
                *(uint32_t*)(C + o0) = pk(silu_f(f0.x) * a[0], silu_f(f0.y) * a[1]);
                *(uint32_t*)(C + o1) = pk(silu_f(f1.x) * a[2], silu_f(f1.y) * a[3]);
            } else {
                float* C = (float*)Cv;
                *(float2*)(C + o0) = make_float2(a[0], a[1]);
                *(float2*)(C + o1) = make_float2(a[2], a[3]);
            }
        }
    }
}

// ---------------- host launcher -------------------------------------------------
extern "C" void kernel_launch(void* const* d_in, const int* in_sizes, int n_in,
                              void* d_out, int out_size) {
    const float* x  = (const float*)d_in[0];
    const float* gw = (const float*)d_in[1];
    const float* uw = (const float*)d_in[2];
    const float* dw = (const float*)d_in[3];
    const int*   gs = (const int*)d_in[4];
    float* out = (float*)d_out;

    // Resolve REAL device addresses of __device__ scratch (host shadow trap).
    void *p_xh = nullptr, *p_gate = nullptr, *p_hid = nullptr, *p_wh = nullptr;
    cudaGetSymbolAddress(&p_xh, g_xh);
    cudaGetSymbolAddress(&p_gate, g_gate);
    cudaGetSymbolAddress(&p_hid, g_hid);
    cudaGetSymbolAddress(&p_wh, g_wh);
    __half* xh   = (__half*)p_xh;
    __half* gate = (__half*)p_gate;
    __half* hid  = (__half*)p_hid;
    __half* wh_g = (__half*)p_wh;                         // gate weights fp16
    __half* wh_u = wh_g + (size_t)NE * HD * ID;           // up weights fp16
    __half* wh_d = wh_u + (size_t)NE * HD * ID;           // down weights fp16

    cudaFuncSetAttribute(gemm_moe<HD, ID, 0>,
                         cudaFuncAttributeMaxDynamicSharedMemorySize, SMEM_DYN);
    cudaFuncSetAttribute(gemm_moe<HD, ID, 1>,
                         cudaFuncAttributeMaxDynamicSharedMemorySize, SMEM_DYN);
    cudaFuncSetAttribute(gemm_moe<ID, HD, 2>,
                         cudaFuncAttributeMaxDynamicSharedMemorySize, SMEM_DYN);

    // fp32 -> fp16 conversions (x and all weights)
    const int nx4 = (TT * HD) / 4;
    cvt_f2h<<<(nx4 + 255) / 256, 256>>>((const float4*)x, xh, nx4);
    const int nw4 = (NE * HD * ID) / 4;
    cvt_f2h<<<(nw4 + 255) / 256, 256>>>((const float4*)gw, wh_g, nw4);
    cvt_f2h<<<(nw4 + 255) / 256, 256>>>((const float4*)uw, wh_u, nw4);
    cvt_f2h<<<(nw4 + 255) / 256, 256>>>((const float4*)dw, wh_d, nw4);

    // gate = x @ gate_w             -> g_gate (fp16)
    gemm_moe<HD, ID, 0><<<dim3(ID / 128, TT / 128), 256, SMEM_DYN>>>(
        xh, wh_g, gate, nullptr, gs);
    // hid = silu(gate) * (x @ up_w) -> g_hid (fp16, fused epilogue)
    gemm_moe<HD, ID, 1><<<dim3(ID / 128, TT / 128), 256, SMEM_DYN>>>(
        xh, wh_u, hid, gate, gs);
    // out = hid @ down_w            -> out (fp32)
    gemm_moe<ID, HD, 2><<<dim3(HD / 128, TT / 128), 256, SMEM_DYN>>>(
        hid, wh_d, out, nullptr, gs);
}